// round 1
// baseline (speedup 1.0000x reference)
#include <cuda_runtime.h>
#include <cuda_bf16.h>

#define N_TOK 16384
#define DIM   1024
#define ODIM  1024
#define NEXP  8
#define TOPK  2

#define TM 64
#define TN 64
#define TK 16

// ---- scratch (static device globals; allocation-free per harness rules) ----
__device__ int           g_count[NEXP];
__device__ int           g_list[NEXP][N_TOK];
__device__ float         g_wt[NEXP][N_TOK];
__device__ unsigned char g_slot[NEXP][N_TOK];
__device__ float         g_partial[TOPK][N_TOK][ODIM];   // ~134 MB

// ---------------------------------------------------------------------------
__global__ void reset_kernel() {
    if (threadIdx.x < NEXP) g_count[threadIdx.x] = 0;
}

// One warp per token: 8 dot products of length 1024, softmax, top-2 push.
__global__ void gate_kernel(const float* __restrict__ x,
                            const float* __restrict__ gw,
                            const float* __restrict__ gb) {
    int warp = (blockIdx.x * blockDim.x + threadIdx.x) >> 5;
    int lane = threadIdx.x & 31;
    if (warp >= N_TOK) return;
    const float* xr = x + (size_t)warp * DIM;

    float acc[NEXP];
#pragma unroll
    for (int e = 0; e < NEXP; e++) acc[e] = 0.f;

    for (int d = lane; d < DIM; d += 32) {
        float xv = xr[d];
        const float* g = gw + d * NEXP;
#pragma unroll
        for (int e = 0; e < NEXP; e++) acc[e] += xv * g[e];
    }
#pragma unroll
    for (int e = 0; e < NEXP; e++) {
#pragma unroll
        for (int off = 16; off > 0; off >>= 1)
            acc[e] += __shfl_down_sync(0xffffffffu, acc[e], off);
    }

    if (lane == 0) {
        float logits[NEXP];
        float mx = -1e30f;
#pragma unroll
        for (int e = 0; e < NEXP; e++) {
            logits[e] = acc[e] + gb[e];
            mx = fmaxf(mx, logits[e]);
        }
        float p[NEXP];
        float sum = 0.f;
#pragma unroll
        for (int e = 0; e < NEXP; e++) { p[e] = expf(logits[e] - mx); sum += p[e]; }
        float inv = 1.f / sum;

        // top-2 by logits (same ordering as softmax probs); strict > keeps
        // lowest index on ties, matching jax.lax.top_k.
        int i0 = 0;
#pragma unroll
        for (int e = 1; e < NEXP; e++) if (logits[e] > logits[i0]) i0 = e;
        int i1 = (i0 == 0) ? 1 : 0;
#pragma unroll
        for (int e = 0; e < NEXP; e++)
            if (e != i0 && logits[e] > logits[i1]) i1 = e;

        int pos0 = atomicAdd(&g_count[i0], 1);
        g_list[i0][pos0] = warp;  g_wt[i0][pos0] = p[i0] * inv;  g_slot[i0][pos0] = 0;
        int pos1 = atomicAdd(&g_count[i1], 1);
        g_list[i1][pos1] = warp;  g_wt[i1][pos1] = p[i1] * inv;  g_slot[i1][pos1] = 1;
    }
}

// Grouped GEMM, expert-major. Block = 64 tokens x 64 outs, K-tile 16.
// 256 threads, each a 4x4 fp32 microtile. Epilogue: w * (acc + bias) into
// per-slot partial (each token appears in exactly one tile per slot -> plain
// stores, no atomics, deterministic).
__global__ __launch_bounds__(256, 4) void moe_gemm_kernel(
    const float* __restrict__ x,
    const float* __restrict__ ew,
    const float* __restrict__ eb)
{
    const int e   = blockIdx.z;
    const int cnt = g_count[e];
    const int m0  = blockIdx.y * TM;
    if (m0 >= cnt) return;
    const int n0  = blockIdx.x * TN;

    __shared__ float As[TK][TM];
    __shared__ float Bs[TK][TN];
    __shared__ int   toks[TM];

    const int tid = threadIdx.x;
    const int tx  = tid & 15;   // output-col group
    const int ty  = tid >> 4;   // token-row group

    if (tid < TM) {
        int idx = m0 + tid;
        toks[tid] = (idx < cnt) ? g_list[e][idx] : g_list[e][m0];  // safe dup
    }
    __syncthreads();

    const float* W = ew + (size_t)e * DIM * ODIM + n0;

    const int a_m = tid >> 2;         // 0..63 token within tile
    const int a_k = (tid & 3) * 4;    // 0..12 k offset (float4)
    const int b_k = tid >> 4;         // 0..15 k row
    const int b_n = (tid & 15) * 4;   // 0..60 out offset (float4)

    const int my_tok = toks[a_m];

    float acc[4][4] = {};

    for (int k0 = 0; k0 < DIM; k0 += TK) {
        // Issue global loads for this stage before the barrier (overlap with
        // previous stage's compute).
        float4 av = *(const float4*)(x + (size_t)my_tok * DIM + k0 + a_k);
        float4 bv = *(const float4*)(W + (size_t)(k0 + b_k) * ODIM + b_n);
        __syncthreads();
        As[a_k + 0][a_m] = av.x;
        As[a_k + 1][a_m] = av.y;
        As[a_k + 2][a_m] = av.z;
        As[a_k + 3][a_m] = av.w;
        *(float4*)&Bs[b_k][b_n] = bv;
        __syncthreads();

#pragma unroll
        for (int kk = 0; kk < TK; kk++) {
            float4 a4 = *(const float4*)&As[kk][ty * 4];
            float4 b4 = *(const float4*)&Bs[kk][tx * 4];
            float ar[4] = {a4.x, a4.y, a4.z, a4.w};
            float br[4] = {b4.x, b4.y, b4.z, b4.w};
#pragma unroll
            for (int i = 0; i < 4; i++)
#pragma unroll
                for (int j = 0; j < 4; j++)
                    acc[i][j] += ar[i] * br[j];
        }
    }

    float4 bias = *(const float4*)(eb + e * ODIM + n0 + tx * 4);

#pragma unroll
    for (int i = 0; i < 4; i++) {
        int ridx = m0 + ty * 4 + i;
        if (ridx >= cnt) continue;
        int tok   = toks[ty * 4 + i];
        float w   = g_wt[e][ridx];
        int  slot = g_slot[e][ridx];
        float4 o;
        o.x = w * (acc[i][0] + bias.x);
        o.y = w * (acc[i][1] + bias.y);
        o.z = w * (acc[i][2] + bias.z);
        o.w = w * (acc[i][3] + bias.w);
        *(float4*)&g_partial[slot][tok][n0 + tx * 4] = o;
    }
}

// out = partial0 + partial1 (every token has exactly 2 slots written).
__global__ void combine_kernel(float* __restrict__ out) {
    size_t i = (size_t)blockIdx.x * blockDim.x + threadIdx.x;
    size_t total = (size_t)N_TOK * ODIM / 4;
    if (i >= total) return;
    const float4* p0 = (const float4*)g_partial[0];
    const float4* p1 = (const float4*)g_partial[1];
    float4 a = p0[i], b = p1[i];
    ((float4*)out)[i] = make_float4(a.x + b.x, a.y + b.y, a.z + b.z, a.w + b.w);
}

// ---------------------------------------------------------------------------
extern "C" void kernel_launch(void* const* d_in, const int* in_sizes, int n_in,
                              void* d_out, int out_size) {
    const float* x  = (const float*)d_in[0];
    const float* gw = (const float*)d_in[1];
    const float* gb = (const float*)d_in[2];
    const float* ew = (const float*)d_in[3];
    const float* eb = (const float*)d_in[4];
    float* out = (float*)d_out;

    reset_kernel<<<1, 32>>>();
    gate_kernel<<<N_TOK / 8, 256>>>(x, gw, gb);

    dim3 grid(ODIM / TN, N_TOK / TM, NEXP);   // worst-case token tiles; blocks early-exit
    moe_gemm_kernel<<<grid, 256>>>(x, ew, eb);

    combine_kernel<<<((size_t)N_TOK * ODIM / 4 + 255) / 256, 256>>>(out);
}

// round 3
// speedup vs baseline: 2.2929x; 2.2929x over previous
#include <cuda_runtime.h>
#include <cuda_bf16.h>
#include <cstdint>

#define N_TOK 16384
#define DIM   1024
#define ODIM  1024
#define NEXP  8

#define TM 128
#define TN 128
#define KC 32
#define NC (DIM / KC)          // 32 k-chunks

// dynamic smem layout
#define SM_TOKS  0             // int[128]
#define SM_W     512           // float[128]
#define SM_SLOT  1024          // int[128]
#define SM_BIAS  1536          // float[128]
#define SM_TILES 2048
#define STAGE_BYTES 32768      // {Ah,Al,Bh,Bl} x 8KB
#define SMEM_BYTES (SM_TILES + 2 * STAGE_BYTES)   // 67584

// ---- scratch ----
__device__ int           g_count[NEXP];
__device__ int           g_list[NEXP][N_TOK];
__device__ float         g_w[NEXP][N_TOK];
__device__ int           g_slot[NEXP][N_TOK];
__device__ float         g_partial[2][N_TOK][ODIM];
__device__ __nv_bfloat16 g_xhi[N_TOK][DIM];
__device__ __nv_bfloat16 g_xlo[N_TOK][DIM];
__device__ __nv_bfloat16 g_wthi[NEXP][ODIM][DIM];   // W^T hi: [e][n][k]
__device__ __nv_bfloat16 g_wtlo[NEXP][ODIM][DIM];

// ===================== helpers =====================
__device__ __forceinline__ uint32_t smem_u32(const void* p) {
    uint32_t a;
    asm("{ .reg .u64 t; cvta.to.shared.u64 t, %1; cvt.u32.u64 %0, t; }"
        : "=r"(a) : "l"(p));
    return a;
}

#define CP_ASYNC16(dst, src) \
    asm volatile("cp.async.cg.shared.global [%0], [%1], 16;" \
                 :: "r"(dst), "l"(src))
#define CP_COMMIT()  asm volatile("cp.async.commit_group;")
#define CP_WAIT1()   asm volatile("cp.async.wait_group 1;")

#define LDSM_X4(r, addr) \
    asm volatile("ldmatrix.sync.aligned.m8n8.x4.shared.b16 {%0,%1,%2,%3}, [%4];" \
                 : "=r"((r)[0]), "=r"((r)[1]), "=r"((r)[2]), "=r"((r)[3]) \
                 : "r"(addr))

#define MMA16816(d, a, b) \
    asm volatile("mma.sync.aligned.m16n8k16.row.col.f32.bf16.bf16.f32 " \
                 "{%0,%1,%2,%3}, {%4,%5,%6,%7}, {%8,%9}, {%0,%1,%2,%3};" \
                 : "+f"((d)[0]), "+f"((d)[1]), "+f"((d)[2]), "+f"((d)[3]) \
                 : "r"((a)[0]), "r"((a)[1]), "r"((a)[2]), "r"((a)[3]), \
                   "r"((b)[0]), "r"((b)[1]))

__device__ __forceinline__ uint32_t split2(float f0, float f1, uint32_t& lo) {
    __nv_bfloat16 h0 = __float2bfloat16(f0);
    __nv_bfloat16 h1 = __float2bfloat16(f1);
    __nv_bfloat16 l0 = __float2bfloat16(f0 - __bfloat162float(h0));
    __nv_bfloat16 l1 = __float2bfloat16(f1 - __bfloat162float(h1));
    __nv_bfloat162 hh; hh.x = h0; hh.y = h1;
    __nv_bfloat162 ll; ll.x = l0; ll.y = l1;
    lo = *reinterpret_cast<uint32_t*>(&ll);
    return *reinterpret_cast<uint32_t*>(&hh);
}

// row is a 64B smem row; two rows per 128B line; xor keeps ldmatrix conflict-free
__device__ __forceinline__ uint32_t swz(int row, int chunk) {
    return (uint32_t)(row * 64 + ((chunk ^ ((row >> 1) & 3)) << 4));
}

// ===================== small kernels =====================
__global__ void reset_kernel() {
    if (threadIdx.x < NEXP) g_count[threadIdx.x] = 0;
}

__global__ void gate_kernel(const float* __restrict__ x,
                            const float* __restrict__ gw,
                            const float* __restrict__ gb) {
    int warp = (blockIdx.x * blockDim.x + threadIdx.x) >> 5;
    int lane = threadIdx.x & 31;
    if (warp >= N_TOK) return;
    const float* xr = x + (size_t)warp * DIM;

    float acc[NEXP];
#pragma unroll
    for (int e = 0; e < NEXP; e++) acc[e] = 0.f;
    for (int d = lane; d < DIM; d += 32) {
        float xv = xr[d];
        const float* g = gw + d * NEXP;
#pragma unroll
        for (int e = 0; e < NEXP; e++) acc[e] += xv * g[e];
    }
#pragma unroll
    for (int e = 0; e < NEXP; e++)
#pragma unroll
        for (int off = 16; off > 0; off >>= 1)
            acc[e] += __shfl_down_sync(0xffffffffu, acc[e], off);

    if (lane == 0) {
        float logits[NEXP];
        float mx = -1e30f;
#pragma unroll
        for (int e = 0; e < NEXP; e++) {
            logits[e] = acc[e] + gb[e];
            mx = fmaxf(mx, logits[e]);
        }
        float p[NEXP], sum = 0.f;
#pragma unroll
        for (int e = 0; e < NEXP; e++) { p[e] = expf(logits[e] - mx); sum += p[e]; }
        float inv = 1.f / sum;

        int i0 = 0;
#pragma unroll
        for (int e = 1; e < NEXP; e++) if (logits[e] > logits[i0]) i0 = e;
        int i1 = (i0 == 0) ? 1 : 0;
#pragma unroll
        for (int e = 0; e < NEXP; e++)
            if (e != i0 && logits[e] > logits[i1]) i1 = e;

        int pos0 = atomicAdd(&g_count[i0], 1);
        g_list[i0][pos0] = warp; g_w[i0][pos0] = p[i0] * inv; g_slot[i0][pos0] = 0;
        int pos1 = atomicAdd(&g_count[i1], 1);
        g_list[i1][pos1] = warp; g_w[i1][pos1] = p[i1] * inv; g_slot[i1][pos1] = 1;
    }
}

// x fp32 -> bf16 hi/lo
__global__ void convx_kernel(const float* __restrict__ x) {
    size_t i = (size_t)blockIdx.x * blockDim.x + threadIdx.x;   // per float4
    if (i >= (size_t)N_TOK * DIM / 4) return;
    float4 v = ((const float4*)x)[i];
    uint32_t l0, l1;
    uint32_t h0 = split2(v.x, v.y, l0);
    uint32_t h1 = split2(v.z, v.w, l1);
    ((uint2*)&g_xhi[0][0])[i] = make_uint2(h0, h1);
    ((uint2*)&g_xlo[0][0])[i] = make_uint2(l0, l1);
}

// transpose + split: ew [e][k][n] fp32 -> g_wthi/lo [e][n][k] bf16
__global__ void convw_kernel(const float* __restrict__ ew) {
    __shared__ float t[32][33];
    int e  = blockIdx.z;
    int k0 = blockIdx.x * 32;
    int n0 = blockIdx.y * 32;
    for (int i = threadIdx.y; i < 32; i += 8)
        t[i][threadIdx.x] = ew[((size_t)e * DIM + k0 + i) * ODIM + n0 + threadIdx.x];
    __syncthreads();
    __nv_bfloat16* wh = &g_wthi[0][0][0];
    __nv_bfloat16* wl = &g_wtlo[0][0][0];
    for (int i = threadIdx.y; i < 32; i += 8) {
        float v = t[threadIdx.x][i];     // k = k0+tx, n = n0+i
        __nv_bfloat16 h = __float2bfloat16(v);
        __nv_bfloat16 l = __float2bfloat16(v - __bfloat162float(h));
        size_t o = ((size_t)e * ODIM + n0 + i) * DIM + k0 + threadIdx.x;
        wh[o] = h; wl[o] = l;
    }
}

// ===================== HMMA grouped GEMM =====================
__global__ __launch_bounds__(256, 1) void moe_mma_kernel(const float* __restrict__ eb)
{
    const int e   = blockIdx.z;
    const int cnt = g_count[e];
    const int m0  = blockIdx.y * TM;
    if (m0 >= cnt) return;
    const int n0  = blockIdx.x * TN;

    extern __shared__ char smem[];
    const uint32_t sb = smem_u32(smem);
    int*   toks_s = (int*)(smem + SM_TOKS);
    float* w_s    = (float*)(smem + SM_W);
    int*   slot_s = (int*)(smem + SM_SLOT);
    float* bias_s = (float*)(smem + SM_BIAS);

    const int tid = threadIdx.x;
    const int wid = tid >> 5;
    const int lid = tid & 31;
    const int warp_m = wid & 3;      // 4 M-groups of 32
    const int warp_n = wid >> 2;     // 2 N-groups of 64

    if (tid < TM) {
        int idx = m0 + tid;
        int src = (idx < cnt) ? idx : m0;
        toks_s[tid] = g_list[e][src];
        w_s[tid]    = g_w[e][src];
        slot_s[tid] = g_slot[e][src];
        bias_s[tid] = eb[e * ODIM + n0 + tid];
    }
    __syncthreads();

    const char* xhiB = (const char*)&g_xhi[0][0];
    const char* xloB = (const char*)&g_xlo[0][0];
    const char* whB  = (const char*)&g_wthi[0][0][0] + (((size_t)e * ODIM + n0) * DIM) * 2;
    const char* wlB  = (const char*)&g_wtlo[0][0][0] + (((size_t)e * ODIM + n0) * DIM) * 2;

    // per-thread load slots: row r (0..127), half h (0/1): chunks 2h, 2h+1
    const int lr = tid >> 1;
    const int lh = tid & 1;
    const int ltok = toks_s[lr];
    const uint32_t so0 = swz(lr, 2 * lh);
    const uint32_t so1 = swz(lr, 2 * lh + 1);
    const size_t aoff = ((size_t)ltok * DIM) * 2 + (size_t)lh * 32;
    const size_t boff = ((size_t)lr * DIM) * 2 + (size_t)lh * 32;

#define LOAD_STAGE(kc, s) do {                                              \
        uint32_t b_ = sb + SM_TILES + (s) * STAGE_BYTES;                    \
        size_t kb_ = (size_t)(kc) * (KC * 2);                               \
        const char* pah = xhiB + aoff + kb_;                                \
        const char* pal = xloB + aoff + kb_;                                \
        const char* pbh = whB  + boff + kb_;                                \
        const char* pbl = wlB  + boff + kb_;                                \
        CP_ASYNC16(b_ + so0,          pah);                                 \
        CP_ASYNC16(b_ + so1,          pah + 16);                            \
        CP_ASYNC16(b_ + 8192  + so0,  pal);                                 \
        CP_ASYNC16(b_ + 8192  + so1,  pal + 16);                            \
        CP_ASYNC16(b_ + 16384 + so0,  pbh);                                 \
        CP_ASYNC16(b_ + 16384 + so1,  pbh + 16);                            \
        CP_ASYNC16(b_ + 24576 + so0,  pbl);                                 \
        CP_ASYNC16(b_ + 24576 + so1,  pbl + 16);                            \
    } while (0)

    LOAD_STAGE(0, 0); CP_COMMIT();
    LOAD_STAGE(1, 1); CP_COMMIT();

    float acc[2][8][4];
#pragma unroll
    for (int i = 0; i < 2; i++)
#pragma unroll
        for (int j = 0; j < 8; j++)
#pragma unroll
            for (int q = 0; q < 4; q++) acc[i][j][q] = 0.f;

    // ldmatrix lane addressing (precompute row/chunk pieces)
    const int a_row = (lid & 15);          // + warp_m*32 + mt*16
    const int a_ch  = (lid >> 4);          // + ks*2
    const int b_nr  = ((lid >> 4) << 3) + (lid & 7);  // + warp_n*64 + bt*16
    const int b_ch  = ((lid >> 3) & 1);    // + ks*2

    for (int kc = 0; kc < NC; kc++) {
        CP_WAIT1();
        __syncthreads();
        uint32_t base = sb + SM_TILES + (kc & 1) * STAGE_BYTES;

#pragma unroll
        for (int ks = 0; ks < 2; ks++) {
            uint32_t ah[2][4], al[2][4];
#pragma unroll
            for (int mt = 0; mt < 2; mt++) {
                int row = warp_m * 32 + mt * 16 + a_row;
                uint32_t off = swz(row, ks * 2 + a_ch);
                LDSM_X4(ah[mt], base + off);
                LDSM_X4(al[mt], base + 8192 + off);
            }
            uint32_t bh[4][4], bl[4][4];
#pragma unroll
            for (int bt = 0; bt < 4; bt++) {
                int n = warp_n * 64 + bt * 16 + b_nr;
                uint32_t off = swz(n, ks * 2 + b_ch);
                LDSM_X4(bh[bt], base + 16384 + off);
                LDSM_X4(bl[bt], base + 24576 + off);
            }
#pragma unroll
            for (int mt = 0; mt < 2; mt++)
#pragma unroll
                for (int nt = 0; nt < 8; nt++) {
                    uint32_t* fh = &bh[nt >> 1][(nt & 1) * 2];
                    uint32_t* fl = &bl[nt >> 1][(nt & 1) * 2];
                    MMA16816(acc[mt][nt], ah[mt], fh);
                    MMA16816(acc[mt][nt], al[mt], fh);
                    MMA16816(acc[mt][nt], ah[mt], fl);
                }
        }
        __syncthreads();
        if (kc + 2 < NC) LOAD_STAGE(kc + 2, kc & 1);
        CP_COMMIT();
    }

    // epilogue: w * (acc + bias) -> partial[slot][tok]
#pragma unroll
    for (int mt = 0; mt < 2; mt++) {
        int r0 = warp_m * 32 + mt * 16 + (lid >> 2);
        int r1 = r0 + 8;
        bool live0 = (m0 + r0) < cnt;
        bool live1 = (m0 + r1) < cnt;
        int   t0 = toks_s[r0],  t1 = toks_s[r1];
        float w0 = w_s[r0],     w1 = w_s[r1];
        int   s0 = slot_s[r0],  s1 = slot_s[r1];
        float* p0 = &g_partial[s0][t0][n0];
        float* p1 = &g_partial[s1][t1][n0];
#pragma unroll
        for (int nt = 0; nt < 8; nt++) {
            int col = warp_n * 64 + nt * 8 + (lid & 3) * 2;
            float b0 = bias_s[col], b1 = bias_s[col + 1];
            if (live0) {
                float2 o = make_float2(w0 * (acc[mt][nt][0] + b0),
                                       w0 * (acc[mt][nt][1] + b1));
                *(float2*)(p0 + col) = o;
            }
            if (live1) {
                float2 o = make_float2(w1 * (acc[mt][nt][2] + b0),
                                       w1 * (acc[mt][nt][3] + b1));
                *(float2*)(p1 + col) = o;
            }
        }
    }
}

__global__ void combine_kernel(float* __restrict__ out) {
    size_t i = (size_t)blockIdx.x * blockDim.x + threadIdx.x;
    size_t total = (size_t)N_TOK * ODIM / 4;
    if (i >= total) return;
    const float4* p0 = (const float4*)g_partial[0];
    const float4* p1 = (const float4*)g_partial[1];
    float4 a = p0[i], b = p1[i];
    ((float4*)out)[i] = make_float4(a.x + b.x, a.y + b.y, a.z + b.z, a.w + b.w);
}

// ===================== launch =====================
extern "C" void kernel_launch(void* const* d_in, const int* in_sizes, int n_in,
                              void* d_out, int out_size) {
    const float* x  = (const float*)d_in[0];
    const float* gw = (const float*)d_in[1];
    const float* gb = (const float*)d_in[2];
    const float* ew = (const float*)d_in[3];
    const float* eb = (const float*)d_in[4];
    float* out = (float*)d_out;

    reset_kernel<<<1, 32>>>();
    gate_kernel<<<N_TOK / 8, 256>>>(x, gw, gb);
    convx_kernel<<<(N_TOK * DIM / 4 + 255) / 256, 256>>>(x);
    convw_kernel<<<dim3(DIM / 32, ODIM / 32, NEXP), dim3(32, 8)>>>(ew);

    static bool attr_set = false;
    if (!attr_set) {
        cudaFuncSetAttribute(moe_mma_kernel,
                             cudaFuncAttributeMaxDynamicSharedMemorySize, SMEM_BYTES);
        attr_set = true;
    }
    dim3 grid(ODIM / TN, N_TOK / TM, NEXP);
    moe_mma_kernel<<<grid, 256, SMEM_BYTES>>>(eb);

    combine_kernel<<<(N_TOK * ODIM / 4 + 255) / 256, 256>>>(out);
}

// round 4
// speedup vs baseline: 2.4008x; 1.0471x over previous
#include <cuda_runtime.h>
#include <cuda_bf16.h>
#include <cstdint>

#define N_TOK 16384
#define DIM   1024
#define ODIM  1024
#define NEXP  8

#define TM 128
#define TN 128
#define KC 32
#define NC (DIM / KC)          // 32 k-chunks
#define NSTAGE 4

// dynamic smem layout
#define SM_TOKS  0             // int[128]
#define SM_W     512           // float[128]
#define SM_SLOT  1024          // int[128]
#define SM_BIAS  1536          // float[128]
#define SM_TILES 2048
#define STAGE_BYTES 32768      // {Ah,Al,Bh,Bl} x 8KB
#define SMEM_BYTES (SM_TILES + NSTAGE * STAGE_BYTES)   // 133120

// ---- scratch ----
__device__ int           g_count[NEXP];
__device__ int           g_list[NEXP][N_TOK];
__device__ float         g_w[NEXP][N_TOK];
__device__ int           g_slot[NEXP][N_TOK];
__device__ float         g_partial[2][N_TOK][ODIM];
__device__ __nv_bfloat16 g_xhi[N_TOK][DIM];
__device__ __nv_bfloat16 g_xlo[N_TOK][DIM];
__device__ __nv_bfloat16 g_wthi[NEXP][ODIM][DIM];   // W^T hi: [e][n][k]
__device__ __nv_bfloat16 g_wtlo[NEXP][ODIM][DIM];

// ===================== helpers =====================
__device__ __forceinline__ uint32_t smem_u32(const void* p) {
    uint32_t a;
    asm("{ .reg .u64 t; cvta.to.shared.u64 t, %1; cvt.u32.u64 %0, t; }"
        : "=r"(a) : "l"(p));
    return a;
}

#define CP_ASYNC16(dst, src) \
    asm volatile("cp.async.cg.shared.global [%0], [%1], 16;" \
                 :: "r"(dst), "l"(src))
#define CP_COMMIT()  asm volatile("cp.async.commit_group;")
#define CP_WAIT2()   asm volatile("cp.async.wait_group 2;")

#define LDSM_X4(r, addr) \
    asm volatile("ldmatrix.sync.aligned.m8n8.x4.shared.b16 {%0,%1,%2,%3}, [%4];" \
                 : "=r"((r)[0]), "=r"((r)[1]), "=r"((r)[2]), "=r"((r)[3]) \
                 : "r"(addr))

#define MMA16816(d, a, b) \
    asm volatile("mma.sync.aligned.m16n8k16.row.col.f32.bf16.bf16.f32 " \
                 "{%0,%1,%2,%3}, {%4,%5,%6,%7}, {%8,%9}, {%0,%1,%2,%3};" \
                 : "+f"((d)[0]), "+f"((d)[1]), "+f"((d)[2]), "+f"((d)[3]) \
                 : "r"((a)[0]), "r"((a)[1]), "r"((a)[2]), "r"((a)[3]), \
                   "r"((b)[0]), "r"((b)[1]))

__device__ __forceinline__ uint32_t split2(float f0, float f1, uint32_t& lo) {
    __nv_bfloat16 h0 = __float2bfloat16(f0);
    __nv_bfloat16 h1 = __float2bfloat16(f1);
    __nv_bfloat16 l0 = __float2bfloat16(f0 - __bfloat162float(h0));
    __nv_bfloat16 l1 = __float2bfloat16(f1 - __bfloat162float(h1));
    __nv_bfloat162 hh; hh.x = h0; hh.y = h1;
    __nv_bfloat162 ll; ll.x = l0; ll.y = l1;
    lo = *reinterpret_cast<uint32_t*>(&ll);
    return *reinterpret_cast<uint32_t*>(&hh);
}

// row is a 64B smem row; two rows per 128B line; xor keeps ldmatrix conflict-free
__device__ __forceinline__ uint32_t swz(int row, int chunk) {
    return (uint32_t)(row * 64 + ((chunk ^ ((row >> 1) & 3)) << 4));
}

// ===================== small kernels =====================
__global__ void reset_kernel() {
    if (threadIdx.x < NEXP) g_count[threadIdx.x] = 0;
}

__global__ void gate_kernel(const float* __restrict__ x,
                            const float* __restrict__ gw,
                            const float* __restrict__ gb) {
    int warp = (blockIdx.x * blockDim.x + threadIdx.x) >> 5;
    int lane = threadIdx.x & 31;
    if (warp >= N_TOK) return;
    const float* xr = x + (size_t)warp * DIM;

    float acc[NEXP];
#pragma unroll
    for (int e = 0; e < NEXP; e++) acc[e] = 0.f;
    for (int d = lane; d < DIM; d += 32) {
        float xv = xr[d];
        const float* g = gw + d * NEXP;
#pragma unroll
        for (int e = 0; e < NEXP; e++) acc[e] += xv * g[e];
    }
#pragma unroll
    for (int e = 0; e < NEXP; e++)
#pragma unroll
        for (int off = 16; off > 0; off >>= 1)
            acc[e] += __shfl_down_sync(0xffffffffu, acc[e], off);

    if (lane == 0) {
        float logits[NEXP];
        float mx = -1e30f;
#pragma unroll
        for (int e = 0; e < NEXP; e++) {
            logits[e] = acc[e] + gb[e];
            mx = fmaxf(mx, logits[e]);
        }
        float p[NEXP], sum = 0.f;
#pragma unroll
        for (int e = 0; e < NEXP; e++) { p[e] = expf(logits[e] - mx); sum += p[e]; }
        float inv = 1.f / sum;

        int i0 = 0;
#pragma unroll
        for (int e = 1; e < NEXP; e++) if (logits[e] > logits[i0]) i0 = e;
        int i1 = (i0 == 0) ? 1 : 0;
#pragma unroll
        for (int e = 0; e < NEXP; e++)
            if (e != i0 && logits[e] > logits[i1]) i1 = e;

        int pos0 = atomicAdd(&g_count[i0], 1);
        g_list[i0][pos0] = warp; g_w[i0][pos0] = p[i0] * inv; g_slot[i0][pos0] = 0;
        int pos1 = atomicAdd(&g_count[i1], 1);
        g_list[i1][pos1] = warp; g_w[i1][pos1] = p[i1] * inv; g_slot[i1][pos1] = 1;
    }
}

// x fp32 -> bf16 hi/lo
__global__ void convx_kernel(const float* __restrict__ x) {
    size_t i = (size_t)blockIdx.x * blockDim.x + threadIdx.x;   // per float4
    if (i >= (size_t)N_TOK * DIM / 4) return;
    float4 v = ((const float4*)x)[i];
    uint32_t l0, l1;
    uint32_t h0 = split2(v.x, v.y, l0);
    uint32_t h1 = split2(v.z, v.w, l1);
    ((uint2*)&g_xhi[0][0])[i] = make_uint2(h0, h1);
    ((uint2*)&g_xlo[0][0])[i] = make_uint2(l0, l1);
}

// transpose + split: ew [e][k][n] fp32 -> g_wthi/lo [e][n][k] bf16
__global__ void convw_kernel(const float* __restrict__ ew) {
    __shared__ float t[32][33];
    int e  = blockIdx.z;
    int k0 = blockIdx.x * 32;
    int n0 = blockIdx.y * 32;
    for (int i = threadIdx.y; i < 32; i += 8)
        t[i][threadIdx.x] = ew[((size_t)e * DIM + k0 + i) * ODIM + n0 + threadIdx.x];
    __syncthreads();
    __nv_bfloat16* wh = &g_wthi[0][0][0];
    __nv_bfloat16* wl = &g_wtlo[0][0][0];
    for (int i = threadIdx.y; i < 32; i += 8) {
        float v = t[threadIdx.x][i];     // k = k0+tx, n = n0+i
        __nv_bfloat16 h = __float2bfloat16(v);
        __nv_bfloat16 l = __float2bfloat16(v - __bfloat162float(h));
        size_t o = ((size_t)e * ODIM + n0 + i) * DIM + k0 + threadIdx.x;
        wh[o] = h; wl[o] = l;
    }
}

// ===================== HMMA grouped GEMM =====================
__global__ __launch_bounds__(256, 1) void moe_mma_kernel(const float* __restrict__ eb)
{
    const int e   = blockIdx.z;
    const int cnt = g_count[e];
    const int m0  = blockIdx.y * TM;
    if (m0 >= cnt) return;
    const int n0  = blockIdx.x * TN;

    extern __shared__ char smem[];
    const uint32_t sb = smem_u32(smem);
    int*   toks_s = (int*)(smem + SM_TOKS);
    float* w_s    = (float*)(smem + SM_W);
    int*   slot_s = (int*)(smem + SM_SLOT);
    float* bias_s = (float*)(smem + SM_BIAS);

    const int tid = threadIdx.x;
    const int wid = tid >> 5;
    const int lid = tid & 31;
    const int warp_m = wid & 3;      // 4 M-groups of 32
    const int warp_n = wid >> 2;     // 2 N-groups of 64

    if (tid < TM) {
        int idx = m0 + tid;
        int src = (idx < cnt) ? idx : m0;
        toks_s[tid] = g_list[e][src];
        w_s[tid]    = g_w[e][src];
        slot_s[tid] = g_slot[e][src];
        bias_s[tid] = eb[e * ODIM + n0 + tid];
    }
    __syncthreads();

    const char* xhiB = (const char*)&g_xhi[0][0];
    const char* xloB = (const char*)&g_xlo[0][0];
    const char* whB  = (const char*)&g_wthi[0][0][0] + (((size_t)e * ODIM + n0) * DIM) * 2;
    const char* wlB  = (const char*)&g_wtlo[0][0][0] + (((size_t)e * ODIM + n0) * DIM) * 2;

    // per-thread load slots: row r (0..127), half h (0/1): chunks 2h, 2h+1
    const int lr = tid >> 1;
    const int lh = tid & 1;
    const int ltok = toks_s[lr];
    const uint32_t so0 = swz(lr, 2 * lh);
    const uint32_t so1 = swz(lr, 2 * lh + 1);
    const size_t aoff = ((size_t)ltok * DIM) * 2 + (size_t)lh * 32;
    const size_t boff = ((size_t)lr * DIM) * 2 + (size_t)lh * 32;

#define LOAD_STAGE(kc, s) do {                                              \
        uint32_t b_ = sb + SM_TILES + (s) * STAGE_BYTES;                    \
        size_t kb_ = (size_t)(kc) * (KC * 2);                               \
        const char* pah = xhiB + aoff + kb_;                                \
        const char* pal = xloB + aoff + kb_;                                \
        const char* pbh = whB  + boff + kb_;                                \
        const char* pbl = wlB  + boff + kb_;                                \
        CP_ASYNC16(b_ + so0,          pah);                                 \
        CP_ASYNC16(b_ + so1,          pah + 16);                            \
        CP_ASYNC16(b_ + 8192  + so0,  pal);                                 \
        CP_ASYNC16(b_ + 8192  + so1,  pal + 16);                            \
        CP_ASYNC16(b_ + 16384 + so0,  pbh);                                 \
        CP_ASYNC16(b_ + 16384 + so1,  pbh + 16);                            \
        CP_ASYNC16(b_ + 24576 + so0,  pbl);                                 \
        CP_ASYNC16(b_ + 24576 + so1,  pbl + 16);                            \
    } while (0)

    LOAD_STAGE(0, 0); CP_COMMIT();
    LOAD_STAGE(1, 1); CP_COMMIT();
    LOAD_STAGE(2, 2); CP_COMMIT();

    float acc[2][8][4];
#pragma unroll
    for (int i = 0; i < 2; i++)
#pragma unroll
        for (int j = 0; j < 8; j++)
#pragma unroll
            for (int q = 0; q < 4; q++) acc[i][j][q] = 0.f;

    // ldmatrix lane addressing (precompute row/chunk pieces)
    const int a_row = (lid & 15);          // + warp_m*32 + mt*16
    const int a_ch  = (lid >> 4);          // + ks*2
    const int b_nr  = ((lid >> 4) << 3) + (lid & 7);  // + warp_n*64 + bt*16
    const int b_ch  = ((lid >> 3) & 1);    // + ks*2

    for (int kc = 0; kc < NC; kc++) {
        // stage kc is ready once <=2 newer groups remain in flight
        CP_WAIT2();
        __syncthreads();
        // refill the stage consumed at kc-1 (all warps are past it: they
        // crossed this barrier only after finishing compute(kc-1))
        if (kc + 3 < NC) LOAD_STAGE(kc + 3, (kc + 3) & 3);
        CP_COMMIT();

        uint32_t base = sb + SM_TILES + (kc & 3) * STAGE_BYTES;

#pragma unroll
        for (int ks = 0; ks < 2; ks++) {
            uint32_t ah[2][4], al[2][4];
#pragma unroll
            for (int mt = 0; mt < 2; mt++) {
                int row = warp_m * 32 + mt * 16 + a_row;
                uint32_t off = swz(row, ks * 2 + a_ch);
                LDSM_X4(ah[mt], base + off);
                LDSM_X4(al[mt], base + 8192 + off);
            }
            uint32_t bh[4][4], bl[4][4];
#pragma unroll
            for (int bt = 0; bt < 4; bt++) {
                int n = warp_n * 64 + bt * 16 + b_nr;
                uint32_t off = swz(n, ks * 2 + b_ch);
                LDSM_X4(bh[bt], base + 16384 + off);
                LDSM_X4(bl[bt], base + 24576 + off);
            }
            // pass-major ordering: each acc is touched once per pass, so
            // HMMA RAW chains are distance-16 instead of back-to-back
#pragma unroll
            for (int mt = 0; mt < 2; mt++)
#pragma unroll
                for (int nt = 0; nt < 8; nt++)
                    MMA16816(acc[mt][nt], ah[mt], (&bh[nt >> 1][(nt & 1) * 2]));
#pragma unroll
            for (int mt = 0; mt < 2; mt++)
#pragma unroll
                for (int nt = 0; nt < 8; nt++)
                    MMA16816(acc[mt][nt], al[mt], (&bh[nt >> 1][(nt & 1) * 2]));
#pragma unroll
            for (int mt = 0; mt < 2; mt++)
#pragma unroll
                for (int nt = 0; nt < 8; nt++)
                    MMA16816(acc[mt][nt], ah[mt], (&bl[nt >> 1][(nt & 1) * 2]));
        }
    }

    // epilogue: w * (acc + bias) -> partial[slot][tok]
#pragma unroll
    for (int mt = 0; mt < 2; mt++) {
        int r0 = warp_m * 32 + mt * 16 + (lid >> 2);
        int r1 = r0 + 8;
        bool live0 = (m0 + r0) < cnt;
        bool live1 = (m0 + r1) < cnt;
        int   t0 = toks_s[r0],  t1 = toks_s[r1];
        float w0 = w_s[r0],     w1 = w_s[r1];
        int   s0 = slot_s[r0],  s1 = slot_s[r1];
        float* p0 = &g_partial[s0][t0][n0];
        float* p1 = &g_partial[s1][t1][n0];
#pragma unroll
        for (int nt = 0; nt < 8; nt++) {
            int col = warp_n * 64 + nt * 8 + (lid & 3) * 2;
            float b0 = bias_s[col], b1 = bias_s[col + 1];
            if (live0) {
                float2 o = make_float2(w0 * (acc[mt][nt][0] + b0),
                                       w0 * (acc[mt][nt][1] + b1));
                *(float2*)(p0 + col) = o;
            }
            if (live1) {
                float2 o = make_float2(w1 * (acc[mt][nt][2] + b0),
                                       w1 * (acc[mt][nt][3] + b1));
                *(float2*)(p1 + col) = o;
            }
        }
    }
}

__global__ void combine_kernel(float* __restrict__ out) {
    size_t i = (size_t)blockIdx.x * blockDim.x + threadIdx.x;
    size_t total = (size_t)N_TOK * ODIM / 4;
    if (i >= total) return;
    const float4* p0 = (const float4*)g_partial[0];
    const float4* p1 = (const float4*)g_partial[1];
    float4 a = p0[i], b = p1[i];
    ((float4*)out)[i] = make_float4(a.x + b.x, a.y + b.y, a.z + b.z, a.w + b.w);
}

// ===================== launch =====================
extern "C" void kernel_launch(void* const* d_in, const int* in_sizes, int n_in,
                              void* d_out, int out_size) {
    const float* x  = (const float*)d_in[0];
    const float* gw = (const float*)d_in[1];
    const float* gb = (const float*)d_in[2];
    const float* ew = (const float*)d_in[3];
    const float* eb = (const float*)d_in[4];
    float* out = (float*)d_out;

    reset_kernel<<<1, 32>>>();
    gate_kernel<<<N_TOK / 8, 256>>>(x, gw, gb);
    convx_kernel<<<(N_TOK * DIM / 4 + 255) / 256, 256>>>(x);
    convw_kernel<<<dim3(DIM / 32, ODIM / 32, NEXP), dim3(32, 8)>>>(ew);

    static bool attr_set = false;
    if (!attr_set) {
        cudaFuncSetAttribute(moe_mma_kernel,
                             cudaFuncAttributeMaxDynamicSharedMemorySize, SMEM_BYTES);
        attr_set = true;
    }
    dim3 grid(ODIM / TN, N_TOK / TM, NEXP);
    moe_mma_kernel<<<grid, 256, SMEM_BYTES>>>(eb);

    combine_kernel<<<(N_TOK * ODIM / 4 + 255) / 256, 256>>>(out);
}

// round 5
// speedup vs baseline: 3.1412x; 1.3084x over previous
#include <cuda_runtime.h>
#include <cuda_fp16.h>
#include <cuda_bf16.h>
#include <cstdint>

#define N_TOK 16384
#define DIM   1024
#define ODIM  1024
#define NEXP  8

#define TM 128
#define TN 128
#define KC 32
#define NC (DIM / KC)          // 32 k-chunks
#define NSTAGE 4
#define WLO_SCALE 2048.0f
#define WLO_INV   (1.0f / 2048.0f)

// dynamic smem layout
#define SM_TOKS  0             // int[128]
#define SM_W     512           // float[128]
#define SM_SLOT  1024          // int[128]
#define SM_BIAS  1536          // float[128]
#define SM_TILES 2048
#define STAGE_BYTES 24576      // {A, Bh, Bl} x 8KB
#define SMEM_BYTES (SM_TILES + NSTAGE * STAGE_BYTES)   // 100352

// ---- scratch ----
__device__ int     g_count[NEXP];
__device__ int     g_list[NEXP][N_TOK];
__device__ float   g_w[NEXP][N_TOK];
__device__ int     g_slot[NEXP][N_TOK];
__device__ float   g_partial[2][N_TOK][ODIM];
__device__ __half  g_xh[N_TOK][DIM];                // fp16(x)
__device__ __half  g_wthi[NEXP][ODIM][DIM];         // W^T hi: [e][n][k]
__device__ __half  g_wtlo[NEXP][ODIM][DIM];         // 2048*(W - hi)

// ===================== helpers =====================
__device__ __forceinline__ uint32_t smem_u32(const void* p) {
    uint32_t a;
    asm("{ .reg .u64 t; cvta.to.shared.u64 t, %1; cvt.u32.u64 %0, t; }"
        : "=r"(a) : "l"(p));
    return a;
}

#define CP_ASYNC16(dst, src) \
    asm volatile("cp.async.cg.shared.global [%0], [%1], 16;" \
                 :: "r"(dst), "l"(src))
#define CP_COMMIT()  asm volatile("cp.async.commit_group;")
#define CP_WAIT2()   asm volatile("cp.async.wait_group 2;")

#define LDSM_X4(r, addr) \
    asm volatile("ldmatrix.sync.aligned.m8n8.x4.shared.b16 {%0,%1,%2,%3}, [%4];" \
                 : "=r"((r)[0]), "=r"((r)[1]), "=r"((r)[2]), "=r"((r)[3]) \
                 : "r"(addr))

// fp16 inputs, fp32 accumulate
#define MMAF32(d, a, b) \
    asm volatile("mma.sync.aligned.m16n8k16.row.col.f32.f16.f16.f32 " \
                 "{%0,%1,%2,%3}, {%4,%5,%6,%7}, {%8,%9}, {%0,%1,%2,%3};" \
                 : "+f"((d)[0]), "+f"((d)[1]), "+f"((d)[2]), "+f"((d)[3]) \
                 : "r"((a)[0]), "r"((a)[1]), "r"((a)[2]), "r"((a)[3]), \
                   "r"((b)[0]), "r"((b)[1]))

// fp16 inputs, fp16 accumulate (used for the scaled low-order pass)
#define MMAF16(d, a, b) \
    asm volatile("mma.sync.aligned.m16n8k16.row.col.f16.f16.f16.f16 " \
                 "{%0,%1}, {%2,%3,%4,%5}, {%6,%7}, {%0,%1};" \
                 : "+r"((d)[0]), "+r"((d)[1]) \
                 : "r"((a)[0]), "r"((a)[1]), "r"((a)[2]), "r"((a)[3]), \
                   "r"((b)[0]), "r"((b)[1]))

// row is a 64B smem row; xor keeps ldmatrix conflict-free
__device__ __forceinline__ uint32_t swz(int row, int chunk) {
    return (uint32_t)(row * 64 + ((chunk ^ ((row >> 1) & 3)) << 4));
}

// ===================== small kernels =====================
__global__ void reset_kernel() {
    if (threadIdx.x < NEXP) g_count[threadIdx.x] = 0;
}

// gate + x->fp16 conversion fused (x row is already in flight here)
__global__ void gate_kernel(const float* __restrict__ x,
                            const float* __restrict__ gw,
                            const float* __restrict__ gb) {
    int warp = (blockIdx.x * blockDim.x + threadIdx.x) >> 5;
    int lane = threadIdx.x & 31;
    if (warp >= N_TOK) return;
    const float* xr = x + (size_t)warp * DIM;
    __half* xh = &g_xh[warp][0];

    float acc[NEXP];
#pragma unroll
    for (int e = 0; e < NEXP; e++) acc[e] = 0.f;
    for (int d = lane; d < DIM; d += 32) {
        float xv = xr[d];
        xh[d] = __float2half_rn(xv);
        const float* g = gw + d * NEXP;
#pragma unroll
        for (int e = 0; e < NEXP; e++) acc[e] += xv * g[e];
    }
#pragma unroll
    for (int e = 0; e < NEXP; e++)
#pragma unroll
        for (int off = 16; off > 0; off >>= 1)
            acc[e] += __shfl_down_sync(0xffffffffu, acc[e], off);

    if (lane == 0) {
        float logits[NEXP];
        float mx = -1e30f;
#pragma unroll
        for (int e = 0; e < NEXP; e++) {
            logits[e] = acc[e] + gb[e];
            mx = fmaxf(mx, logits[e]);
        }
        float p[NEXP], sum = 0.f;
#pragma unroll
        for (int e = 0; e < NEXP; e++) { p[e] = expf(logits[e] - mx); sum += p[e]; }
        float inv = 1.f / sum;

        int i0 = 0;
#pragma unroll
        for (int e = 1; e < NEXP; e++) if (logits[e] > logits[i0]) i0 = e;
        int i1 = (i0 == 0) ? 1 : 0;
#pragma unroll
        for (int e = 0; e < NEXP; e++)
            if (e != i0 && logits[e] > logits[i1]) i1 = e;

        int pos0 = atomicAdd(&g_count[i0], 1);
        g_list[i0][pos0] = warp; g_w[i0][pos0] = p[i0] * inv; g_slot[i0][pos0] = 0;
        int pos1 = atomicAdd(&g_count[i1], 1);
        g_list[i1][pos1] = warp; g_w[i1][pos1] = p[i1] * inv; g_slot[i1][pos1] = 1;
    }
}

// transpose + fp16 split: ew [e][k][n] fp32 -> Whi, 2048*Wlo  [e][n][k]
__global__ void convw_kernel(const float* __restrict__ ew) {
    __shared__ float t[32][33];
    int e  = blockIdx.z;
    int k0 = blockIdx.x * 32;
    int n0 = blockIdx.y * 32;
    for (int i = threadIdx.y; i < 32; i += 8)
        t[i][threadIdx.x] = ew[((size_t)e * DIM + k0 + i) * ODIM + n0 + threadIdx.x];
    __syncthreads();
    __half* wh = &g_wthi[0][0][0];
    __half* wl = &g_wtlo[0][0][0];
    for (int i = threadIdx.y; i < 32; i += 8) {
        float v = t[threadIdx.x][i];     // k = k0+tx, n = n0+i
        __half h = __float2half_rn(v);
        __half l = __float2half_rn((v - __half2float(h)) * WLO_SCALE);
        size_t o = ((size_t)e * ODIM + n0 + i) * DIM + k0 + threadIdx.x;
        wh[o] = h; wl[o] = l;
    }
}

// ===================== HMMA grouped GEMM (2-pass fp16) =====================
__global__ __launch_bounds__(256, 1) void moe_mma_kernel(const float* __restrict__ eb)
{
    const int e   = blockIdx.z;
    const int cnt = g_count[e];
    const int m0  = blockIdx.y * TM;
    if (m0 >= cnt) return;
    const int n0  = blockIdx.x * TN;

    extern __shared__ char smem[];
    const uint32_t sb = smem_u32(smem);
    int*   toks_s = (int*)(smem + SM_TOKS);
    float* w_s    = (float*)(smem + SM_W);
    int*   slot_s = (int*)(smem + SM_SLOT);
    float* bias_s = (float*)(smem + SM_BIAS);

    const int tid = threadIdx.x;
    const int wid = tid >> 5;
    const int lid = tid & 31;
    const int warp_m = wid & 3;      // 4 M-groups of 32
    const int warp_n = wid >> 2;     // 2 N-groups of 64

    if (tid < TM) {
        int idx = m0 + tid;
        int src = (idx < cnt) ? idx : m0;
        toks_s[tid] = g_list[e][src];
        w_s[tid]    = g_w[e][src];
        slot_s[tid] = g_slot[e][src];
        bias_s[tid] = eb[e * ODIM + n0 + tid];
    }
    __syncthreads();

    const char* xB  = (const char*)&g_xh[0][0];
    const char* whB = (const char*)&g_wthi[0][0][0] + (((size_t)e * ODIM + n0) * DIM) * 2;
    const char* wlB = (const char*)&g_wtlo[0][0][0] + (((size_t)e * ODIM + n0) * DIM) * 2;

    // per-thread load slots: row r (0..127), half h (0/1): chunks 2h, 2h+1
    const int lr = tid >> 1;
    const int lh = tid & 1;
    const int ltok = toks_s[lr];
    const uint32_t so0 = swz(lr, 2 * lh);
    const uint32_t so1 = swz(lr, 2 * lh + 1);
    const size_t aoff = ((size_t)ltok * DIM) * 2 + (size_t)lh * 32;
    const size_t boff = ((size_t)lr * DIM) * 2 + (size_t)lh * 32;

#define LOAD_STAGE(kc, s) do {                                              \
        uint32_t b_ = sb + SM_TILES + (s) * STAGE_BYTES;                    \
        size_t kb_ = (size_t)(kc) * (KC * 2);                               \
        const char* pa  = xB  + aoff + kb_;                                 \
        const char* pbh = whB + boff + kb_;                                 \
        const char* pbl = wlB + boff + kb_;                                 \
        CP_ASYNC16(b_ + so0,          pa);                                  \
        CP_ASYNC16(b_ + so1,          pa + 16);                             \
        CP_ASYNC16(b_ + 8192  + so0,  pbh);                                 \
        CP_ASYNC16(b_ + 8192  + so1,  pbh + 16);                            \
        CP_ASYNC16(b_ + 16384 + so0,  pbl);                                 \
        CP_ASYNC16(b_ + 16384 + so1,  pbl + 16);                            \
    } while (0)

    LOAD_STAGE(0, 0); CP_COMMIT();
    LOAD_STAGE(1, 1); CP_COMMIT();
    LOAD_STAGE(2, 2); CP_COMMIT();

    float acc[2][8][4];
#pragma unroll
    for (int i = 0; i < 2; i++)
#pragma unroll
        for (int j = 0; j < 8; j++)
#pragma unroll
            for (int q = 0; q < 4; q++) acc[i][j][q] = 0.f;
    uint32_t accl[2][8][2];
#pragma unroll
    for (int i = 0; i < 2; i++)
#pragma unroll
        for (int j = 0; j < 8; j++) { accl[i][j][0] = 0u; accl[i][j][1] = 0u; }

    const int a_row = (lid & 15);
    const int a_ch  = (lid >> 4);
    const int b_nr  = ((lid >> 4) << 3) + (lid & 7);
    const int b_ch  = ((lid >> 3) & 1);

    for (int kc = 0; kc < NC; kc++) {
        CP_WAIT2();
        __syncthreads();
        if (kc + 3 < NC) LOAD_STAGE(kc + 3, (kc + 3) & 3);
        CP_COMMIT();

        uint32_t base = sb + SM_TILES + (kc & 3) * STAGE_BYTES;

#pragma unroll
        for (int ks = 0; ks < 2; ks++) {
            uint32_t av[2][4];
#pragma unroll
            for (int mt = 0; mt < 2; mt++) {
                int row = warp_m * 32 + mt * 16 + a_row;
                LDSM_X4(av[mt], base + swz(row, ks * 2 + a_ch));
            }
            uint32_t bh[4][4], bl[4][4];
#pragma unroll
            for (int bt = 0; bt < 4; bt++) {
                int n = warp_n * 64 + bt * 16 + b_nr;
                uint32_t off = swz(n, ks * 2 + b_ch);
                LDSM_X4(bh[bt], base + 8192 + off);
                LDSM_X4(bl[bt], base + 16384 + off);
            }
            // pass 1: x*Whi, fp32 accumulate
#pragma unroll
            for (int mt = 0; mt < 2; mt++)
#pragma unroll
                for (int nt = 0; nt < 8; nt++)
                    MMAF32(acc[mt][nt], av[mt], (&bh[nt >> 1][(nt & 1) * 2]));
            // pass 2: x*(2048*Wlo), fp16 accumulate
#pragma unroll
            for (int mt = 0; mt < 2; mt++)
#pragma unroll
                for (int nt = 0; nt < 8; nt++)
                    MMAF16(accl[mt][nt], av[mt], (&bl[nt >> 1][(nt & 1) * 2]));
        }
    }

    // epilogue: w * (acc_hi + acc_lo/2048 + bias) -> partial[slot][tok]
#pragma unroll
    for (int mt = 0; mt < 2; mt++) {
        int r0 = warp_m * 32 + mt * 16 + (lid >> 2);
        int r1 = r0 + 8;
        bool live0 = (m0 + r0) < cnt;
        bool live1 = (m0 + r1) < cnt;
        int   t0 = toks_s[r0],  t1 = toks_s[r1];
        float w0 = w_s[r0],     w1 = w_s[r1];
        int   s0 = slot_s[r0],  s1 = slot_s[r1];
        float* p0 = &g_partial[s0][t0][n0];
        float* p1 = &g_partial[s1][t1][n0];
#pragma unroll
        for (int nt = 0; nt < 8; nt++) {
            int col = warp_n * 64 + nt * 8 + (lid & 3) * 2;
            float b0 = bias_s[col], b1 = bias_s[col + 1];
            float2 lo01 = __half22float2(*(__half2*)&accl[mt][nt][0]);
            float2 lo23 = __half22float2(*(__half2*)&accl[mt][nt][1]);
            if (live0) {
                float2 o = make_float2(
                    w0 * (acc[mt][nt][0] + lo01.x * WLO_INV + b0),
                    w0 * (acc[mt][nt][1] + lo01.y * WLO_INV + b1));
                *(float2*)(p0 + col) = o;
            }
            if (live1) {
                float2 o = make_float2(
                    w1 * (acc[mt][nt][2] + lo23.x * WLO_INV + b0),
                    w1 * (acc[mt][nt][3] + lo23.y * WLO_INV + b1));
                *(float2*)(p1 + col) = o;
            }
        }
    }
}

__global__ void combine_kernel(float* __restrict__ out) {
    size_t i = (size_t)blockIdx.x * blockDim.x + threadIdx.x;
    size_t total = (size_t)N_TOK * ODIM / 4;
    if (i >= total) return;
    const float4* p0 = (const float4*)g_partial[0];
    const float4* p1 = (const float4*)g_partial[1];
    float4 a = p0[i], b = p1[i];
    ((float4*)out)[i] = make_float4(a.x + b.x, a.y + b.y, a.z + b.z, a.w + b.w);
}

// ===================== launch =====================
extern "C" void kernel_launch(void* const* d_in, const int* in_sizes, int n_in,
                              void* d_out, int out_size) {
    const float* x  = (const float*)d_in[0];
    const float* gw = (const float*)d_in[1];
    const float* gb = (const float*)d_in[2];
    const float* ew = (const float*)d_in[3];
    const float* eb = (const float*)d_in[4];
    float* out = (float*)d_out;

    reset_kernel<<<1, 32>>>();
    gate_kernel<<<N_TOK / 8, 256>>>(x, gw, gb);
    convw_kernel<<<dim3(DIM / 32, ODIM / 32, NEXP), dim3(32, 8)>>>(ew);

    static bool attr_set = false;
    if (!attr_set) {
        cudaFuncSetAttribute(moe_mma_kernel,
                             cudaFuncAttributeMaxDynamicSharedMemorySize, SMEM_BYTES);
        attr_set = true;
    }
    dim3 grid(ODIM / TN, N_TOK / TM, NEXP);
    moe_mma_kernel<<<grid, 256, SMEM_BYTES>>>(eb);

    combine_kernel<<<(N_TOK * ODIM / 4 + 255) / 256, 256>>>(out);
}

// round 6
// speedup vs baseline: 3.2453x; 1.0332x over previous
#include <cuda_runtime.h>
#include <cuda_fp16.h>
#include <cstdint>

#define N_TOK 16384
#define DIM   1024
#define ODIM  1024
#define NEXP  8

#define TM 128
#define TN 128
#define KC 32
#define NC (DIM / KC)          // 32 k-chunks
#define NSTAGE 4
#define WLO_SCALE 2048.0f
#define WLO_INV   (1.0f / 2048.0f)

// dynamic smem layout
#define SM_TOKS  0             // int[128]
#define SM_W     512           // float[128]
#define SM_SLOT  1024          // int[128]
#define SM_BIAS  1536          // float[128]
#define SM_TILES 2048
#define STAGE_BYTES 24576      // {A, Bh, Bl} x 8KB
#define SMEM_BYTES (SM_TILES + NSTAGE * STAGE_BYTES)   // 100352

// ---- scratch ----
__device__ int     g_count[NEXP];
__device__ int     g_list[NEXP][N_TOK];
__device__ float   g_w[NEXP][N_TOK];
__device__ int     g_slot[NEXP][N_TOK];
__device__ float   g_partial[2][N_TOK][ODIM];
__device__ __half  g_xh[N_TOK][DIM];                // fp16(x)
__device__ __half  g_wthi[NEXP][ODIM][DIM];         // W^T hi: [e][n][k]
__device__ __half  g_wtlo[NEXP][ODIM][DIM];         // 2048*(W - hi)

// ===================== helpers =====================
__device__ __forceinline__ uint32_t smem_u32(const void* p) {
    uint32_t a;
    asm("{ .reg .u64 t; cvta.to.shared.u64 t, %1; cvt.u32.u64 %0, t; }"
        : "=r"(a) : "l"(p));
    return a;
}

#define CP_ASYNC16(dst, src) \
    asm volatile("cp.async.cg.shared.global [%0], [%1], 16;" \
                 :: "r"(dst), "l"(src))
#define CP_COMMIT()  asm volatile("cp.async.commit_group;")
#define CP_WAIT2()   asm volatile("cp.async.wait_group 2;")
#define CP_WAIT1()   asm volatile("cp.async.wait_group 1;")

#define LDSM_X4(r, addr) \
    asm volatile("ldmatrix.sync.aligned.m8n8.x4.shared.b16 {%0,%1,%2,%3}, [%4];" \
                 : "=r"((r)[0]), "=r"((r)[1]), "=r"((r)[2]), "=r"((r)[3]) \
                 : "r"(addr))

// fp16 inputs, fp32 accumulate
#define MMAF32(d, a, b) \
    asm volatile("mma.sync.aligned.m16n8k16.row.col.f32.f16.f16.f32 " \
                 "{%0,%1,%2,%3}, {%4,%5,%6,%7}, {%8,%9}, {%0,%1,%2,%3};" \
                 : "+f"((d)[0]), "+f"((d)[1]), "+f"((d)[2]), "+f"((d)[3]) \
                 : "r"((a)[0]), "r"((a)[1]), "r"((a)[2]), "r"((a)[3]), \
                   "r"((b)[0]), "r"((b)[1]))

// fp16 inputs, fp16 accumulate (scaled low-order pass)
#define MMAF16(d, a, b) \
    asm volatile("mma.sync.aligned.m16n8k16.row.col.f16.f16.f16.f16 " \
                 "{%0,%1}, {%2,%3,%4,%5}, {%6,%7}, {%0,%1};" \
                 : "+r"((d)[0]), "+r"((d)[1]) \
                 : "r"((a)[0]), "r"((a)[1]), "r"((a)[2]), "r"((a)[3]), \
                   "r"((b)[0]), "r"((b)[1]))

// row is a 64B smem row; xor keeps ldmatrix conflict-free
__device__ __forceinline__ uint32_t swz(int row, int chunk) {
    return (uint32_t)(row * 64 + ((chunk ^ ((row >> 1) & 3)) << 4));
}

// ===================== small kernels =====================
__global__ void reset_kernel() {
    if (threadIdx.x < NEXP) g_count[threadIdx.x] = 0;
}

// gate + x->fp16 conversion fused
__global__ void gate_kernel(const float* __restrict__ x,
                            const float* __restrict__ gw,
                            const float* __restrict__ gb) {
    int warp = (blockIdx.x * blockDim.x + threadIdx.x) >> 5;
    int lane = threadIdx.x & 31;
    if (warp >= N_TOK) return;
    const float* xr = x + (size_t)warp * DIM;
    __half* xh = &g_xh[warp][0];

    float acc[NEXP];
#pragma unroll
    for (int e = 0; e < NEXP; e++) acc[e] = 0.f;
    for (int d = lane; d < DIM; d += 32) {
        float xv = xr[d];
        xh[d] = __float2half_rn(xv);
        const float* g = gw + d * NEXP;
#pragma unroll
        for (int e = 0; e < NEXP; e++) acc[e] += xv * g[e];
    }
#pragma unroll
    for (int e = 0; e < NEXP; e++)
#pragma unroll
        for (int off = 16; off > 0; off >>= 1)
            acc[e] += __shfl_down_sync(0xffffffffu, acc[e], off);

    if (lane == 0) {
        float logits[NEXP];
        float mx = -1e30f;
#pragma unroll
        for (int e = 0; e < NEXP; e++) {
            logits[e] = acc[e] + gb[e];
            mx = fmaxf(mx, logits[e]);
        }
        float p[NEXP], sum = 0.f;
#pragma unroll
        for (int e = 0; e < NEXP; e++) { p[e] = expf(logits[e] - mx); sum += p[e]; }
        float inv = 1.f / sum;

        int i0 = 0;
#pragma unroll
        for (int e = 1; e < NEXP; e++) if (logits[e] > logits[i0]) i0 = e;
        int i1 = (i0 == 0) ? 1 : 0;
#pragma unroll
        for (int e = 0; e < NEXP; e++)
            if (e != i0 && logits[e] > logits[i1]) i1 = e;

        int pos0 = atomicAdd(&g_count[i0], 1);
        g_list[i0][pos0] = warp; g_w[i0][pos0] = p[i0] * inv; g_slot[i0][pos0] = 0;
        int pos1 = atomicAdd(&g_count[i1], 1);
        g_list[i1][pos1] = warp; g_w[i1][pos1] = p[i1] * inv; g_slot[i1][pos1] = 1;
    }
}

// transpose + fp16 split: ew [e][k][n] fp32 -> Whi, 2048*Wlo  [e][n][k]
__global__ void convw_kernel(const float* __restrict__ ew) {
    __shared__ float t[32][33];
    int e  = blockIdx.z;
    int k0 = blockIdx.x * 32;
    int n0 = blockIdx.y * 32;
    for (int i = threadIdx.y; i < 32; i += 8)
        t[i][threadIdx.x] = ew[((size_t)e * DIM + k0 + i) * ODIM + n0 + threadIdx.x];
    __syncthreads();
    __half* wh = &g_wthi[0][0][0];
    __half* wl = &g_wtlo[0][0][0];
    for (int i = threadIdx.y; i < 32; i += 8) {
        float v = t[threadIdx.x][i];
        __half h = __float2half_rn(v);
        __half l = __float2half_rn((v - __half2float(h)) * WLO_SCALE);
        size_t o = ((size_t)e * ODIM + n0 + i) * DIM + k0 + threadIdx.x;
        wh[o] = h; wl[o] = l;
    }
}

// ===================== HMMA grouped GEMM (2-pass fp16, frag-pipelined) ======
__global__ __launch_bounds__(256, 1) void moe_mma_kernel(const float* __restrict__ eb)
{
    const int e   = blockIdx.z;
    const int cnt = g_count[e];
    const int m0  = blockIdx.y * TM;
    if (m0 >= cnt) return;
    const int n0  = blockIdx.x * TN;

    extern __shared__ char smem[];
    const uint32_t sb = smem_u32(smem);
    int*   toks_s = (int*)(smem + SM_TOKS);
    float* w_s    = (float*)(smem + SM_W);
    int*   slot_s = (int*)(smem + SM_SLOT);
    float* bias_s = (float*)(smem + SM_BIAS);

    const int tid = threadIdx.x;
    const int wid = tid >> 5;
    const int lid = tid & 31;
    const int warp_m = wid & 3;
    const int warp_n = wid >> 2;

    if (tid < TM) {
        int idx = m0 + tid;
        int src = (idx < cnt) ? idx : m0;
        toks_s[tid] = g_list[e][src];
        w_s[tid]    = g_w[e][src];
        slot_s[tid] = g_slot[e][src];
        bias_s[tid] = eb[e * ODIM + n0 + tid];
    }
    __syncthreads();

    const char* xB  = (const char*)&g_xh[0][0];
    const char* whB = (const char*)&g_wthi[0][0][0] + (((size_t)e * ODIM + n0) * DIM) * 2;
    const char* wlB = (const char*)&g_wtlo[0][0][0] + (((size_t)e * ODIM + n0) * DIM) * 2;

    const int lr = tid >> 1;
    const int lh = tid & 1;
    const int ltok = toks_s[lr];
    const uint32_t so0 = swz(lr, 2 * lh);
    const uint32_t so1 = swz(lr, 2 * lh + 1);
    const size_t aoff = ((size_t)ltok * DIM) * 2 + (size_t)lh * 32;
    const size_t boff = ((size_t)lr * DIM) * 2 + (size_t)lh * 32;

#define LOAD_STAGE(kc, s) do {                                              \
        uint32_t b_ = sb + SM_TILES + (s) * STAGE_BYTES;                    \
        size_t kb_ = (size_t)(kc) * (KC * 2);                               \
        const char* pa  = xB  + aoff + kb_;                                 \
        const char* pbh = whB + boff + kb_;                                 \
        const char* pbl = wlB + boff + kb_;                                 \
        CP_ASYNC16(b_ + so0,          pa);                                  \
        CP_ASYNC16(b_ + so1,          pa + 16);                             \
        CP_ASYNC16(b_ + 8192  + so0,  pbh);                                 \
        CP_ASYNC16(b_ + 8192  + so1,  pbh + 16);                            \
        CP_ASYNC16(b_ + 16384 + so0,  pbl);                                 \
        CP_ASYNC16(b_ + 16384 + so1,  pbl + 16);                            \
    } while (0)

    LOAD_STAGE(0, 0); CP_COMMIT();
    LOAD_STAGE(1, 1); CP_COMMIT();
    LOAD_STAGE(2, 2); CP_COMMIT();

    float acc[2][8][4];
#pragma unroll
    for (int i = 0; i < 2; i++)
#pragma unroll
        for (int j = 0; j < 8; j++)
#pragma unroll
            for (int q = 0; q < 4; q++) acc[i][j][q] = 0.f;
    uint32_t accl[2][8][2];
#pragma unroll
    for (int i = 0; i < 2; i++)
#pragma unroll
        for (int j = 0; j < 8; j++) { accl[i][j][0] = 0u; accl[i][j][1] = 0u; }

    const int a_row = (lid & 15);
    const int a_ch  = (lid >> 4);
    const int b_nr  = ((lid >> 4) << 3) + (lid & 7);
    const int b_ch  = ((lid >> 3) & 1);

    // fragment double buffers: av/bh per-ks, bl single (latency hidden by f32 pass)
    uint32_t av[2][2][4], bh[2][4][4], bl[4][4];

#define LOAD_AB(buf, base, ks) do {                                         \
        _Pragma("unroll")                                                   \
        for (int mt = 0; mt < 2; mt++) {                                    \
            int row = warp_m * 32 + mt * 16 + a_row;                        \
            LDSM_X4(av[buf][mt], (base) + swz(row, (ks) * 2 + a_ch));       \
        }                                                                   \
        _Pragma("unroll")                                                   \
        for (int bt = 0; bt < 4; bt++) {                                    \
            int n = warp_n * 64 + bt * 16 + b_nr;                           \
            LDSM_X4(bh[buf][bt], (base) + 8192 + swz(n, (ks) * 2 + b_ch));  \
        }                                                                   \
    } while (0)

#define LOAD_BL(base, ks) do {                                              \
        _Pragma("unroll")                                                   \
        for (int bt = 0; bt < 4; bt++) {                                    \
            int n = warp_n * 64 + bt * 16 + b_nr;                           \
            LDSM_X4(bl[bt], (base) + 16384 + swz(n, (ks) * 2 + b_ch));      \
        }                                                                   \
    } while (0)

#define PASS_F32(buf)                                                       \
        _Pragma("unroll")                                                   \
        for (int mt = 0; mt < 2; mt++)                                      \
            _Pragma("unroll")                                               \
            for (int nt = 0; nt < 8; nt++)                                  \
                MMAF32(acc[mt][nt], av[buf][mt], (&bh[buf][nt >> 1][(nt & 1) * 2]))

#define PASS_F16(buf)                                                       \
        _Pragma("unroll")                                                   \
        for (int mt = 0; mt < 2; mt++)                                      \
            _Pragma("unroll")                                               \
            for (int nt = 0; nt < 8; nt++)                                  \
                MMAF16(accl[mt][nt], av[buf][mt], (&bl[nt >> 1][(nt & 1) * 2]))

    // preamble: stage 0 complete + visible, then preload fragments (0,0)
    CP_WAIT2();
    __syncthreads();
    {
        uint32_t base0 = sb + SM_TILES + 0 * STAGE_BYTES;
        LOAD_AB(0, base0, 0);
    }

    for (int kc = 0; kc < NC; kc++) {
        uint32_t base  = sb + SM_TILES + (kc & 3) * STAGE_BYTES;

        // ---- ks = 0: frags already in buf0 ----
        LOAD_BL(base, 0);          // bl(kc,0) — covered by f32 pass below
        LOAD_AB(1, base, 1);       // prefetch (kc,1)
        PASS_F32(0);
        PASS_F16(0);

        // ---- pipeline bookkeeping (mid-iteration) ----
        CP_WAIT1();                // stage kc+1 complete (commits through kc+2)
        __syncthreads();           // visibility + all warps done reading stage kc-1
        if (kc + 3 < NC) { LOAD_STAGE(kc + 3, (kc + 3) & 3); }
        CP_COMMIT();

        // ---- ks = 1: frags in buf1 ----
        LOAD_BL(base, 1);
        {
            int nkc = (kc + 1 < NC) ? kc + 1 : kc;      // clamp (dead compute on last)
            uint32_t nbase = sb + SM_TILES + (nkc & 3) * STAGE_BYTES;
            LOAD_AB(0, nbase, 0);  // prefetch (kc+1,0)
        }
        PASS_F32(1);
        PASS_F16(1);
    }

    // epilogue: w * (acc_hi + acc_lo/2048 + bias) -> partial[slot][tok]
#pragma unroll
    for (int mt = 0; mt < 2; mt++) {
        int r0 = warp_m * 32 + mt * 16 + (lid >> 2);
        int r1 = r0 + 8;
        bool live0 = (m0 + r0) < cnt;
        bool live1 = (m0 + r1) < cnt;
        int   t0 = toks_s[r0],  t1 = toks_s[r1];
        float w0 = w_s[r0],     w1 = w_s[r1];
        int   s0 = slot_s[r0],  s1 = slot_s[r1];
        float* p0 = &g_partial[s0][t0][n0];
        float* p1 = &g_partial[s1][t1][n0];
#pragma unroll
        for (int nt = 0; nt < 8; nt++) {
            int col = warp_n * 64 + nt * 8 + (lid & 3) * 2;
            float b0 = bias_s[col], b1 = bias_s[col + 1];
            float2 lo01 = __half22float2(*(__half2*)&accl[mt][nt][0]);
            float2 lo23 = __half22float2(*(__half2*)&accl[mt][nt][1]);
            if (live0) {
                float2 o = make_float2(
                    w0 * (acc[mt][nt][0] + lo01.x * WLO_INV + b0),
                    w0 * (acc[mt][nt][1] + lo01.y * WLO_INV + b1));
                *(float2*)(p0 + col) = o;
            }
            if (live1) {
                float2 o = make_float2(
                    w1 * (acc[mt][nt][2] + lo23.x * WLO_INV + b0),
                    w1 * (acc[mt][nt][3] + lo23.y * WLO_INV + b1));
                *(float2*)(p1 + col) = o;
            }
        }
    }
}

__global__ void combine_kernel(float* __restrict__ out) {
    size_t i = (size_t)blockIdx.x * blockDim.x + threadIdx.x;
    size_t total = (size_t)N_TOK * ODIM / 4;
    if (i >= total) return;
    const float4* p0 = (const float4*)g_partial[0];
    const float4* p1 = (const float4*)g_partial[1];
    float4 a = p0[i], b = p1[i];
    ((float4*)out)[i] = make_float4(a.x + b.x, a.y + b.y, a.z + b.z, a.w + b.w);
}

// ===================== launch =====================
extern "C" void kernel_launch(void* const* d_in, const int* in_sizes, int n_in,
                              void* d_out, int out_size) {
    const float* x  = (const float*)d_in[0];
    const float* gw = (const float*)d_in[1];
    const float* gb = (const float*)d_in[2];
    const float* ew = (const float*)d_in[3];
    const float* eb = (const float*)d_in[4];
    float* out = (float*)d_out;

    reset_kernel<<<1, 32>>>();
    gate_kernel<<<N_TOK / 8, 256>>>(x, gw, gb);
    convw_kernel<<<dim3(DIM / 32, ODIM / 32, NEXP), dim3(32, 8)>>>(ew);

    static bool attr_set = false;
    if (!attr_set) {
        cudaFuncSetAttribute(moe_mma_kernel,
                             cudaFuncAttributeMaxDynamicSharedMemorySize, SMEM_BYTES);
        attr_set = true;
    }
    dim3 grid(ODIM / TN, N_TOK / TM, NEXP);
    moe_mma_kernel<<<grid, 256, SMEM_BYTES>>>(eb);

    combine_kernel<<<(N_TOK * ODIM / 4 + 255) / 256, 256>>>(out);
}